// round 5
// baseline (speedup 1.0000x reference)
#include <cuda_runtime.h>
#include <math_constants.h>

// Fixed shapes
#define B     32
#define H     8192
#define HO    4096
#define W4    64          // 256 floats / 4
#define GPB   128         // blocks (groups) per batch
#define ROWS  32          // output rows per block
#define RPT   8           // output rows per thread (ROWS / 4 subs)
#define DELTA 2           // normalize lag (batches)
#define NBLK  (B * GPB)          // 4096 pooling blocks
#define NTAIL (DELTA * GPB)      // 256 tail normalizer blocks
#define NTOT  (NBLK + NTAIL)     // 4352

// Per-batch sync/reduction state. Static-initialized for the first launch;
// the last normalizer of each batch resets it for the next graph replay.
__device__ unsigned g_min[B] = {
    0xFFFFFFFFu,0xFFFFFFFFu,0xFFFFFFFFu,0xFFFFFFFFu,0xFFFFFFFFu,0xFFFFFFFFu,0xFFFFFFFFu,0xFFFFFFFFu,
    0xFFFFFFFFu,0xFFFFFFFFu,0xFFFFFFFFu,0xFFFFFFFFu,0xFFFFFFFFu,0xFFFFFFFFu,0xFFFFFFFFu,0xFFFFFFFFu,
    0xFFFFFFFFu,0xFFFFFFFFu,0xFFFFFFFFu,0xFFFFFFFFu,0xFFFFFFFFu,0xFFFFFFFFu,0xFFFFFFFFu,0xFFFFFFFFu,
    0xFFFFFFFFu,0xFFFFFFFFu,0xFFFFFFFFu,0xFFFFFFFFu,0xFFFFFFFFu,0xFFFFFFFFu,0xFFFFFFFFu,0xFFFFFFFFu};
__device__ unsigned g_max[B];        // zero-init == encoded -inf side
__device__ int g_pool_cnt[B];        // zero-init
__device__ int g_done_cnt[B];        // zero-init

__device__ __forceinline__ unsigned enc_f(float f) {
    unsigned u = __float_as_uint(f);
    return (u & 0x80000000u) ? ~u : (u | 0x80000000u);
}
__device__ __forceinline__ float dec_f(unsigned e) {
    unsigned u = (e & 0x80000000u) ? (e ^ 0x80000000u) : ~e;
    return __uint_as_float(u);
}

// Normalize tile (bb, grp) in place in d_out. Assumes pool_cnt[bb] already
// spun to completion by the caller (tid==0) followed by __syncthreads().
__device__ __forceinline__ void normalize_tile(float4* __restrict__ out,
                                               int bb, int grp,
                                               int w4, int sub) {
    const float mnv = dec_f(*(volatile unsigned*)&g_min[bb]);
    const float mxv = dec_f(*(volatile unsigned*)&g_max[bb]);
    const float inv = 1.0f / (mxv - mnv);
    const int r0 = grp * ROWS + sub * RPT;
    float4* __restrict__ ob = out + (size_t)bb * HO * W4;
    #pragma unroll
    for (int i = 0; i < RPT; i++) {
        float4 p = __ldcg(&ob[(size_t)(r0 + i) * W4 + w4]);   // L2 hit (hot line)
        p.x = (p.x - mnv) * inv;
        p.y = (p.y - mnv) * inv;
        p.z = (p.z - mnv) * inv;
        p.w = (p.w - mnv) * inv;
        __stcs(&ob[(size_t)(r0 + i) * W4 + w4], p);           // overwrite in place
    }
    __syncthreads();
    if (threadIdx.x == 0) {
        int d = atomicAdd(&g_done_cnt[bb], 1);
        if (d == GPB - 1) {       // last normalizer: reset state for next replay
            *(volatile unsigned*)&g_min[bb] = 0xFFFFFFFFu;
            *(volatile unsigned*)&g_max[bb] = 0x00000000u;
            *(volatile int*)&g_pool_cnt[bb] = 0;
            *(volatile int*)&g_done_cnt[bb] = 0;
            __threadfence();
        }
    }
}

__global__ __launch_bounds__(256, 8)
void fused_kernel(const float4* __restrict__ x, float4* __restrict__ out) {
    __shared__ float s_mn[8], s_mx[8];

    const int tid  = threadIdx.x;
    const int w4   = tid & 63;
    const int sub  = tid >> 6;           // 0..3
    const int lane = tid & 31;
    const int wid  = tid >> 5;

    const int blk = blockIdx.x;

    if (blk >= NBLK) {
        // -------- Tail normalizer block: batches B-DELTA .. B-1 ----------
        const int idx = blk - NBLK;
        const int bb  = B - DELTA + (idx >> 7);
        const int grp = idx & (GPB - 1);
        if (tid == 0) {
            while (*(volatile int*)&g_pool_cnt[bb] < GPB) __nanosleep(64);
        }
        __syncthreads();
        __threadfence();
        normalize_tile(out, bb, grp, w4, sub);
        return;
    }

    const int b   = blk >> 7;            // batch (batch-major block order)
    const int grp = blk & (GPB - 1);     // row-group within batch
    const int r0  = grp * ROWS + sub * RPT;

    const float4* __restrict__ xb = x + (size_t)b * H * W4;
    float4* __restrict__ ob = out + (size_t)b * HO * W4;

    // ---- Phase 1: pool 8 output rows -> d_out (un-normalized), min/max ----
    float4 prev;
    if (r0 == 0) {
        prev = make_float4(-CUDART_INF_F, -CUDART_INF_F, -CUDART_INF_F, -CUDART_INF_F);
    } else {
        prev = __ldcs(&xb[(size_t)(2 * r0 - 1) * W4 + w4]);
    }
    float mn =  CUDART_INF_F;
    float mx = -CUDART_INF_F;
    #pragma unroll
    for (int i = 0; i < RPT; i++) {
        const int r = r0 + i;
        float4 a = __ldcs(&xb[(size_t)(2 * r)     * W4 + w4]);
        float4 c = __ldcs(&xb[(size_t)(2 * r + 1) * W4 + w4]);
        float4 p;
        p.x = fmaxf(fmaxf(a.x, c.x), prev.x);
        p.y = fmaxf(fmaxf(a.y, c.y), prev.y);
        p.z = fmaxf(fmaxf(a.z, c.z), prev.z);
        p.w = fmaxf(fmaxf(a.w, c.w), prev.w);
        __stcg(&ob[(size_t)r * W4 + w4], p);   // keep in L2; overwritten soon
        mn = fminf(mn, fminf(fminf(p.x, p.y), fminf(p.z, p.w)));
        mx = fmaxf(mx, fmaxf(fmaxf(p.x, p.y), fmaxf(p.z, p.w)));
        prev = c;
    }
    __threadfence();   // make pooled stores device-visible before counter bump

    // ---- Block reduce min/max, publish ----
    #pragma unroll
    for (int off = 16; off > 0; off >>= 1) {
        mn = fminf(mn, __shfl_xor_sync(0xFFFFFFFFu, mn, off));
        mx = fmaxf(mx, __shfl_xor_sync(0xFFFFFFFFu, mx, off));
    }
    if (lane == 0) { s_mn[wid] = mn; s_mx[wid] = mx; }
    __syncthreads();
    if (wid == 0) {
        mn = (lane < 8) ? s_mn[lane] :  CUDART_INF_F;
        mx = (lane < 8) ? s_mx[lane] : -CUDART_INF_F;
        #pragma unroll
        for (int off = 4; off > 0; off >>= 1) {
            mn = fminf(mn, __shfl_xor_sync(0xFFFFFFFFu, mn, off));
            mx = fmaxf(mx, __shfl_xor_sync(0xFFFFFFFFu, mx, off));
        }
        if (lane == 0) {
            atomicMin(&g_min[b], enc_f(mn));
            atomicMax(&g_max[b], enc_f(mx));
            __threadfence();                        // release
            atomicAdd(&g_pool_cnt[b], 1);
        }
    }

    // ---- Phase 2: normalize tile of batch b-DELTA (already pooled) ----
    if (b >= DELTA) {
        const int bb = b - DELTA;
        if (tid == 0) {
            while (*(volatile int*)&g_pool_cnt[bb] < GPB) __nanosleep(64);
        }
        __syncthreads();
        __threadfence();                            // acquire
        normalize_tile(out, bb, grp, w4, sub);
    }
}

extern "C" void kernel_launch(void* const* d_in, const int* in_sizes, int n_in,
                              void* d_out, int out_size) {
    (void)in_sizes; (void)n_in; (void)out_size;
    const float4* x = (const float4*)d_in[0];
    float4* out = (float4*)d_out;
    fused_kernel<<<NTOT, 256>>>(x, out);
}